// round 2
// baseline (speedup 1.0000x reference)
#include <cuda_runtime.h>
#include <cuda_bf16.h>
#include <math.h>

// ---------------------------------------------------------------------------
// MLA forward, B=1, S=2048, HIDDEN=2048, H=16, D=128, R=64, KVC=512, QC=1024
// Round 2: fp32 baseline (fixed input unpacking). One templated 128x128x8
// SIMT SGEMM (TN & NN), batched over heads; materialized scores + row softmax;
// RoPE folded into a packing pass (positions = head index, per reference).
// ---------------------------------------------------------------------------

#define SEQ     2048
#define HID     2048
#define NH      16
#define HD      128
#define RD      64
#define KVC     512
#define QC      1024
#define DKR     (HD + RD)        // 192
#define HDK     (NH * DKR)       // 3072

// ------------------------- scratch (device globals) ------------------------
__device__ float g_kv_c [SEQ * KVC];          // [S, 512]
__device__ float g_q_c  [SEQ * QC];           // [S, 1024]
__device__ float g_kcraw[SEQ * HID];          // keys_c raw   [S, 2048]
__device__ float g_qcraw[SEQ * HID];          // queries_c raw[S, 2048]
__device__ float g_kr   [SEQ * NH * RD];      // key rope raw [S, 1024]
__device__ float g_qr   [SEQ * NH * RD];      // q rope raw   [S, 1024]
__device__ float g_K    [SEQ * HDK];          // [S, H, 192]
__device__ float g_Q    [SEQ * HDK];          // [S, H, 192]
__device__ float g_V    [SEQ * HID];          // [S, H, 128] contiguous
__device__ float g_S    [(size_t)NH * SEQ * SEQ]; // 16 * 2048 * 2048
__device__ float g_ctx  [SEQ * HID];          // [S, H, 128]

// ------------------------------ SGEMM --------------------------------------
// C[z] = alpha * A[z] * op(B[z]) + bias   (op = B^T if TRANSB, else B)
// A: [M,K] row-major (lda); B: TRANSB ? [N,K] : [K,N] row-major (ldb)
// Requires: M%128==0, N%128==0, K%8==0, lda/ldb/ldc %4==0, 16B-aligned bases.
template<bool TRANSB>
__global__ __launch_bounds__(256)
void sgemm(int M, int N, int K, float alpha,
           const float* __restrict__ A, int lda, size_t strideA,
           const float* __restrict__ B, int ldb, size_t strideB,
           const float* __restrict__ bias,
           float* __restrict__ C, int ldc, size_t strideC)
{
    constexpr int BM = 128, BN = 128, BK = 8, TM = 8, TN = 8;
    __shared__ float As[BK][BM];
    __shared__ float Bs[BK][BN];

    A += (size_t)blockIdx.z * strideA;
    B += (size_t)blockIdx.z * strideB;
    C += (size_t)blockIdx.z * strideC;

    const int m0 = blockIdx.y * BM;
    const int n0 = blockIdx.x * BN;
    const int tid = threadIdx.x;
    const int tr = tid >> 4;     // 0..15
    const int tc = tid & 15;     // 0..15

    float acc[TM][TN];
    #pragma unroll
    for (int i = 0; i < TM; i++)
        #pragma unroll
        for (int j = 0; j < TN; j++) acc[i][j] = 0.f;

    for (int k0 = 0; k0 < K; k0 += BK) {
        // ---- load A tile: 128 rows x 8 k, one float4 per thread, transposed
        {
            const int r  = tid >> 1;
            const int c4 = (tid & 1) * 4;
            const float4 v = *reinterpret_cast<const float4*>(
                &A[(size_t)(m0 + r) * lda + k0 + c4]);
            As[c4 + 0][r] = v.x; As[c4 + 1][r] = v.y;
            As[c4 + 2][r] = v.z; As[c4 + 3][r] = v.w;
        }
        // ---- load B tile
        if (TRANSB) {
            const int r  = tid >> 1;          // n index
            const int c4 = (tid & 1) * 4;     // k index
            const float4 v = *reinterpret_cast<const float4*>(
                &B[(size_t)(n0 + r) * ldb + k0 + c4]);
            Bs[c4 + 0][r] = v.x; Bs[c4 + 1][r] = v.y;
            Bs[c4 + 2][r] = v.z; Bs[c4 + 3][r] = v.w;
        } else {
            const int r  = tid >> 5;          // k index 0..7
            const int c4 = (tid & 31) * 4;    // n index
            *reinterpret_cast<float4*>(&Bs[r][c4]) =
                *reinterpret_cast<const float4*>(
                    &B[(size_t)(k0 + r) * ldb + n0 + c4]);
        }
        __syncthreads();

        #pragma unroll
        for (int kk = 0; kk < BK; kk++) {
            float4 a0 = *reinterpret_cast<const float4*>(&As[kk][tr * TM]);
            float4 a1 = *reinterpret_cast<const float4*>(&As[kk][tr * TM + 4]);
            float4 b0 = *reinterpret_cast<const float4*>(&Bs[kk][tc * TN]);
            float4 b1 = *reinterpret_cast<const float4*>(&Bs[kk][tc * TN + 4]);
            float ra[TM] = {a0.x, a0.y, a0.z, a0.w, a1.x, a1.y, a1.z, a1.w};
            float rb[TN] = {b0.x, b0.y, b0.z, b0.w, b1.x, b1.y, b1.z, b1.w};
            #pragma unroll
            for (int i = 0; i < TM; i++)
                #pragma unroll
                for (int j = 0; j < TN; j++)
                    acc[i][j] = fmaf(ra[i], rb[j], acc[i][j]);
        }
        __syncthreads();
    }

    // ---- epilogue
    float bb[TN];
    #pragma unroll
    for (int j = 0; j < TN; j++)
        bb[j] = bias ? bias[n0 + tc * TN + j] : 0.f;

    #pragma unroll
    for (int i = 0; i < TM; i++) {
        const size_t row = (size_t)(m0 + tr * TM + i);
        float4 o0, o1;
        o0.x = alpha * acc[i][0] + bb[0]; o0.y = alpha * acc[i][1] + bb[1];
        o0.z = alpha * acc[i][2] + bb[2]; o0.w = alpha * acc[i][3] + bb[3];
        o1.x = alpha * acc[i][4] + bb[4]; o1.y = alpha * acc[i][5] + bb[5];
        o1.z = alpha * acc[i][6] + bb[6]; o1.w = alpha * acc[i][7] + bb[7];
        *reinterpret_cast<float4*>(&C[row * ldc + n0 + tc * TN])     = o0;
        *reinterpret_cast<float4*>(&C[row * ldc + n0 + tc * TN + 4]) = o1;
    }
}

// -------------------------- pack / rope kernels ----------------------------
// Copy compressed part: raw [S, H*128] -> dst [S, H, 192] at offset 0..127.
__global__ __launch_bounds__(256)
void pack_c(const float* __restrict__ raw, float* __restrict__ dst)
{
    int idx = blockIdx.x * 256 + threadIdx.x;   // over S*2048
    int s = idx >> 11;
    int rem = idx & 2047;
    int h = rem >> 7;
    int d = rem & 127;
    dst[(size_t)s * HDK + h * DKR + d] = raw[idx];
}

// RoPE with positions = head index (faithful to reference), then write into
// dst [S, H, 192] at offsets 128..191.
__global__ __launch_bounds__(256)
void pack_rope(const float* __restrict__ raw, float* __restrict__ dst)
{
    int idx = blockIdx.x * 256 + threadIdx.x;   // over S*16*32 pairs
    int s = idx >> 9;
    int rem = idx & 511;
    int h = rem >> 5;
    int p = rem & 31;
    const float* in = raw + (size_t)s * (NH * RD) + h * RD + 2 * p;
    float x1 = in[0];
    float x2 = in[1];
    float inv_freq = powf(10000.0f, -(2.0f * p) / (float)RD);
    float ang = (float)h * inv_freq;
    float sn, cs;
    sincosf(ang, &sn, &cs);
    float* o = dst + (size_t)s * HDK + h * DKR + HD + 2 * p;
    o[0] = x1 * cs - x2 * sn;
    o[1] = x1 * sn + x2 * cs;
}

// ------------------------------ softmax ------------------------------------
// One block per row of 2048, 256 threads, 8 elems/thread.
__global__ __launch_bounds__(256)
void softmax_rows(float* __restrict__ S)
{
    float* p = S + (size_t)blockIdx.x * SEQ;
    const int t = threadIdx.x;
    const int lane = t & 31, warp = t >> 5;
    __shared__ float sm[8];

    float v[8];
    float m = -1e30f;
    #pragma unroll
    for (int i = 0; i < 8; i++) { v[i] = p[t + 256 * i]; m = fmaxf(m, v[i]); }
    #pragma unroll
    for (int o = 16; o; o >>= 1) m = fmaxf(m, __shfl_xor_sync(~0u, m, o));
    if (lane == 0) sm[warp] = m;
    __syncthreads();
    float bm = sm[0];
    #pragma unroll
    for (int i = 1; i < 8; i++) bm = fmaxf(bm, sm[i]);
    __syncthreads();

    float s = 0.f;
    #pragma unroll
    for (int i = 0; i < 8; i++) { v[i] = __expf(v[i] - bm); s += v[i]; }
    #pragma unroll
    for (int o = 16; o; o >>= 1) s += __shfl_xor_sync(~0u, s, o);
    if (lane == 0) sm[warp] = s;
    __syncthreads();
    float tot = 0.f;
    #pragma unroll
    for (int i = 0; i < 8; i++) tot += sm[i];
    const float inv = 1.0f / tot;
    #pragma unroll
    for (int i = 0; i < 8; i++) p[t + 256 * i] = v[i] * inv;
}

// ------------------------------- launch ------------------------------------
static float* sym(const void* s)
{
    void* p = nullptr;
    cudaGetSymbolAddress(&p, s);
    return (float*)p;
}

extern "C" void kernel_launch(void* const* d_in, const int* in_sizes, int n_in,
                              void* d_out, int out_size)
{
    const float* x            = (const float*)d_in[0];
    const float* kv_down_w    = (const float*)d_in[1];
    const float* kv_down_b    = (const float*)d_in[2];
    const float* key_up_w     = (const float*)d_in[3];
    const float* key_up_b     = (const float*)d_in[4];
    const float* value_up_w   = (const float*)d_in[5];
    const float* value_up_b   = (const float*)d_in[6];
    const float* key_rope_w   = (const float*)d_in[7];
    const float* key_rope_b   = (const float*)d_in[8];
    const float* query_down_w = (const float*)d_in[9];
    const float* query_down_b = (const float*)d_in[10];
    const float* query_up_w   = (const float*)d_in[11];
    const float* query_up_b   = (const float*)d_in[12];
    const float* query_rope_w = (const float*)d_in[13];
    const float* query_rope_b = (const float*)d_in[14];
    const float* out_w        = (const float*)d_in[15];
    const float* out_b        = (const float*)d_in[16];
    float* out = (float*)d_out;

    float* kv_c  = sym(g_kv_c);
    float* q_c   = sym(g_q_c);
    float* kcraw = sym(g_kcraw);
    float* qcraw = sym(g_qcraw);
    float* kr    = sym(g_kr);
    float* qr    = sym(g_qr);
    float* Kbuf  = sym(g_K);
    float* Qbuf  = sym(g_Q);
    float* Vbuf  = sym(g_V);
    float* Sbuf  = sym(g_S);
    float* ctx   = sym(g_ctx);

    const float scale = 1.0f / sqrtf((float)DKR);
    auto grid = [](int M, int N, int Z) { return dim3(N / 128, M / 128, Z); };

    // down projections
    sgemm<true><<<grid(SEQ, KVC, 1), 256>>>(SEQ, KVC, HID, 1.f,
        x, HID, 0, kv_down_w, HID, 0, kv_down_b, kv_c, KVC, 0);
    sgemm<true><<<grid(SEQ, QC, 1), 256>>>(SEQ, QC, HID, 1.f,
        x, HID, 0, query_down_w, HID, 0, query_down_b, q_c, QC, 0);

    // up projections
    sgemm<true><<<grid(SEQ, HID, 1), 256>>>(SEQ, HID, KVC, 1.f,
        kv_c, KVC, 0, key_up_w, KVC, 0, key_up_b, kcraw, HID, 0);
    sgemm<true><<<grid(SEQ, HID, 1), 256>>>(SEQ, HID, KVC, 1.f,
        kv_c, KVC, 0, value_up_w, KVC, 0, value_up_b, Vbuf, HID, 0);
    sgemm<true><<<grid(SEQ, NH * RD, 1), 256>>>(SEQ, NH * RD, KVC, 1.f,
        kv_c, KVC, 0, key_rope_w, KVC, 0, key_rope_b, kr, NH * RD, 0);
    sgemm<true><<<grid(SEQ, HID, 1), 256>>>(SEQ, HID, QC, 1.f,
        q_c, QC, 0, query_up_w, QC, 0, query_up_b, qcraw, HID, 0);
    sgemm<true><<<grid(SEQ, NH * RD, 1), 256>>>(SEQ, NH * RD, QC, 1.f,
        q_c, QC, 0, query_rope_w, QC, 0, query_rope_b, qr, NH * RD, 0);

    // pack into [S, H, 192] with RoPE
    pack_c<<<SEQ * HID / 256, 256>>>(kcraw, Kbuf);
    pack_rope<<<SEQ * NH * 32 / 256, 256>>>(kr, Kbuf);
    pack_c<<<SEQ * HID / 256, 256>>>(qcraw, Qbuf);
    pack_rope<<<SEQ * NH * 32 / 256, 256>>>(qr, Qbuf);

    // scores = scale * Q K^T  (batched over heads)
    sgemm<true><<<grid(SEQ, SEQ, NH), 256>>>(SEQ, SEQ, DKR, scale,
        Qbuf, HDK, (size_t)DKR, Kbuf, HDK, (size_t)DKR, nullptr,
        Sbuf, SEQ, (size_t)SEQ * SEQ);

    // softmax over last dim
    softmax_rows<<<NH * SEQ, 256>>>(Sbuf);

    // ctx = P @ V  (batched over heads, NN)
    sgemm<false><<<grid(SEQ, HD, NH), 256>>>(SEQ, HD, SEQ, 1.f,
        Sbuf, SEQ, (size_t)SEQ * SEQ, Vbuf, HID, (size_t)HD, nullptr,
        ctx, HID, (size_t)HD);

    // output projection
    sgemm<true><<<grid(SEQ, HID, 1), 256>>>(SEQ, HID, HID, 1.f,
        ctx, HID, 0, out_w, HID, 0, out_b, out, HID, 0);
}

// round 3
// speedup vs baseline: 4.0190x; 4.0190x over previous
#include <cuda_runtime.h>
#include <cuda_bf16.h>
#include <math.h>
#include <stdint.h>

// ---------------------------------------------------------------------------
// MLA forward, B=1, S=2048, HIDDEN=2048, H=16, D=128, R=64, KVC=512, QC=1024
// Round 3: all GEMMs on tensor cores via mma.sync.m16n8k8.tf32 (fp32 in/out,
// tf32 conversion with cvt.rna on the smem path). 128x128x16 block tile,
// 2x4 warps of 64x32, conflict-free smem (stride 136). Softmax/pack as before.
// ---------------------------------------------------------------------------

#define SEQ     2048
#define HID     2048
#define NH      16
#define HD      128
#define RD      64
#define KVC     512
#define QC      1024
#define DKR     (HD + RD)        // 192
#define HDK     (NH * DKR)       // 3072

// ------------------------- scratch (device globals) ------------------------
__device__ float g_kv_c [SEQ * KVC];
__device__ float g_q_c  [SEQ * QC];
__device__ float g_kcraw[SEQ * HID];
__device__ float g_qcraw[SEQ * HID];
__device__ float g_kr   [SEQ * NH * RD];
__device__ float g_qr   [SEQ * NH * RD];
__device__ float g_K    [SEQ * HDK];
__device__ float g_Q    [SEQ * HDK];
__device__ float g_V    [SEQ * HID];
__device__ float g_S    [(size_t)NH * SEQ * SEQ];
__device__ float g_ctx  [SEQ * HID];

// --------------------------- tf32 helpers ----------------------------------
__device__ __forceinline__ uint32_t f2tf32(float f)
{
    uint32_t r;
    asm("cvt.rna.tf32.f32 %0, %1;" : "=r"(r) : "f"(f));
    return r;
}

__device__ __forceinline__ void mma_tf32(float* c, const uint32_t* a, const uint32_t* b)
{
    asm volatile(
        "mma.sync.aligned.m16n8k8.row.col.f32.tf32.tf32.f32 "
        "{%0,%1,%2,%3}, {%4,%5,%6,%7}, {%8,%9}, {%0,%1,%2,%3};"
        : "+f"(c[0]), "+f"(c[1]), "+f"(c[2]), "+f"(c[3])
        : "r"(a[0]), "r"(a[1]), "r"(a[2]), "r"(a[3]), "r"(b[0]), "r"(b[1]));
}

// ------------------------------ TF32 GEMM ----------------------------------
// C[z] = alpha * A[z] * op(B[z]) + bias   (op = B^T if TRANSB, else B)
// A: [M,K] row-major; B: TRANSB ? [N,K] : [K,N] row-major.
// Requires: M%128==0, N%128==0, K%16==0, 16B-aligned rows.
template<bool TRANSB>
__global__ __launch_bounds__(256, 2)
void tgemm(int M, int N, int K, float alpha,
           const float* __restrict__ A, int lda, size_t strideA,
           const float* __restrict__ B, int ldb, size_t strideB,
           const float* __restrict__ bias,
           float* __restrict__ C, int ldc, size_t strideC)
{
    constexpr int BM = 128, BN = 128, BK = 16, LDSS = 136;
    __shared__ uint32_t As[BK][LDSS];
    __shared__ uint32_t Bs[BK][LDSS];

    A += (size_t)blockIdx.z * strideA;
    B += (size_t)blockIdx.z * strideB;
    C += (size_t)blockIdx.z * strideC;

    const int m0 = blockIdx.y * BM;
    const int n0 = blockIdx.x * BN;
    const int tid  = threadIdx.x;
    const int wid  = tid >> 5;
    const int lane = tid & 31;
    const int wm = (wid >> 2) * 64;      // 2 warps in M
    const int wn = (wid & 3) * 32;       // 4 warps in N
    const int g = lane >> 2;             // 0..7
    const int t = lane & 3;              // 0..3

    const int alr = tid >> 1;            // 0..127 (tile row for A / TN-B)
    const int alc = (tid & 1) * 8;       // 0 or 8 (k base)
    const int bkr = tid >> 5;            // 0..7   (NN-B k row)
    const int bnc = (lane) * 4;          // 0..124 (NN-B n col)

    float acc[4][4][4];
    #pragma unroll
    for (int mt = 0; mt < 4; mt++)
        #pragma unroll
        for (int nt = 0; nt < 4; nt++)
            #pragma unroll
            for (int i = 0; i < 4; i++) acc[mt][nt][i] = 0.f;

    float4 pa0, pa1, pb0, pb1;

    auto gload = [&](int k0) {
        const float* ar = &A[(size_t)(m0 + alr) * lda + k0 + alc];
        pa0 = *reinterpret_cast<const float4*>(ar);
        pa1 = *reinterpret_cast<const float4*>(ar + 4);
        if (TRANSB) {
            const float* br = &B[(size_t)(n0 + alr) * ldb + k0 + alc];
            pb0 = *reinterpret_cast<const float4*>(br);
            pb1 = *reinterpret_cast<const float4*>(br + 4);
        } else {
            pb0 = *reinterpret_cast<const float4*>(&B[(size_t)(k0 + bkr) * ldb + n0 + bnc]);
            pb1 = *reinterpret_cast<const float4*>(&B[(size_t)(k0 + bkr + 8) * ldb + n0 + bnc]);
        }
    };
    auto sstore = [&]() {
        const float* a0 = reinterpret_cast<const float*>(&pa0);
        const float* a1 = reinterpret_cast<const float*>(&pa1);
        #pragma unroll
        for (int j = 0; j < 4; j++) {
            As[alc + j][alr]     = f2tf32(a0[j]);
            As[alc + 4 + j][alr] = f2tf32(a1[j]);
        }
        const float* b0 = reinterpret_cast<const float*>(&pb0);
        const float* b1 = reinterpret_cast<const float*>(&pb1);
        if (TRANSB) {
            #pragma unroll
            for (int j = 0; j < 4; j++) {
                Bs[alc + j][alr]     = f2tf32(b0[j]);
                Bs[alc + 4 + j][alr] = f2tf32(b1[j]);
            }
        } else {
            #pragma unroll
            for (int j = 0; j < 4; j++) {
                Bs[bkr][bnc + j]     = f2tf32(b0[j]);
                Bs[bkr + 8][bnc + j] = f2tf32(b1[j]);
            }
        }
    };

    gload(0);
    sstore();
    __syncthreads();

    for (int k0 = 0; k0 < K; k0 += BK) {
        const bool more = (k0 + BK) < K;
        if (more) gload(k0 + BK);

        #pragma unroll
        for (int ks = 0; ks < BK; ks += 8) {
            uint32_t af[4][4], bf[4][2];
            #pragma unroll
            for (int mt = 0; mt < 4; mt++) {
                const int m = wm + mt * 16 + g;
                af[mt][0] = As[ks + t][m];
                af[mt][1] = As[ks + t][m + 8];
                af[mt][2] = As[ks + t + 4][m];
                af[mt][3] = As[ks + t + 4][m + 8];
            }
            #pragma unroll
            for (int nt = 0; nt < 4; nt++) {
                const int n = wn + nt * 8 + g;
                bf[nt][0] = Bs[ks + t][n];
                bf[nt][1] = Bs[ks + t + 4][n];
            }
            #pragma unroll
            for (int mt = 0; mt < 4; mt++)
                #pragma unroll
                for (int nt = 0; nt < 4; nt++)
                    mma_tf32(acc[mt][nt], af[mt], bf[nt]);
        }
        __syncthreads();
        if (more) {
            sstore();
            __syncthreads();
        }
    }

    // ---- epilogue
    #pragma unroll
    for (int mt = 0; mt < 4; mt++) {
        const int r0 = m0 + wm + mt * 16 + g;
        #pragma unroll
        for (int nt = 0; nt < 4; nt++) {
            const int c = n0 + wn + nt * 8 + 2 * t;
            const float b0v = bias ? bias[c]     : 0.f;
            const float b1v = bias ? bias[c + 1] : 0.f;
            float2 v0, v1;
            v0.x = alpha * acc[mt][nt][0] + b0v;
            v0.y = alpha * acc[mt][nt][1] + b1v;
            v1.x = alpha * acc[mt][nt][2] + b0v;
            v1.y = alpha * acc[mt][nt][3] + b1v;
            *reinterpret_cast<float2*>(&C[(size_t)r0 * ldc + c])       = v0;
            *reinterpret_cast<float2*>(&C[(size_t)(r0 + 8) * ldc + c]) = v1;
        }
    }
}

// -------------------------- pack / rope kernels ----------------------------
__global__ __launch_bounds__(256)
void pack_c(const float* __restrict__ raw, float* __restrict__ dst)
{
    int idx = blockIdx.x * 256 + threadIdx.x;   // over S*2048
    int s = idx >> 11;
    int rem = idx & 2047;
    int h = rem >> 7;
    int d = rem & 127;
    dst[(size_t)s * HDK + h * DKR + d] = raw[idx];
}

__global__ __launch_bounds__(256)
void pack_rope(const float* __restrict__ raw, float* __restrict__ dst)
{
    int idx = blockIdx.x * 256 + threadIdx.x;   // over S*16*32 pairs
    int s = idx >> 9;
    int rem = idx & 511;
    int h = rem >> 5;
    int p = rem & 31;
    const float* in = raw + (size_t)s * (NH * RD) + h * RD + 2 * p;
    float x1 = in[0];
    float x2 = in[1];
    float inv_freq = powf(10000.0f, -(2.0f * p) / (float)RD);
    float ang = (float)h * inv_freq;
    float sn, cs;
    sincosf(ang, &sn, &cs);
    float* o = dst + (size_t)s * HDK + h * DKR + HD + 2 * p;
    o[0] = x1 * cs - x2 * sn;
    o[1] = x1 * sn + x2 * cs;
}

// ------------------------------ softmax ------------------------------------
__global__ __launch_bounds__(256)
void softmax_rows(float* __restrict__ S)
{
    float* p = S + (size_t)blockIdx.x * SEQ;
    const int t = threadIdx.x;
    const int lane = t & 31, warp = t >> 5;
    __shared__ float sm[8];

    float v[8];
    float m = -1e30f;
    #pragma unroll
    for (int i = 0; i < 8; i++) { v[i] = p[t + 256 * i]; m = fmaxf(m, v[i]); }
    #pragma unroll
    for (int o = 16; o; o >>= 1) m = fmaxf(m, __shfl_xor_sync(~0u, m, o));
    if (lane == 0) sm[warp] = m;
    __syncthreads();
    float bm = sm[0];
    #pragma unroll
    for (int i = 1; i < 8; i++) bm = fmaxf(bm, sm[i]);
    __syncthreads();

    float s = 0.f;
    #pragma unroll
    for (int i = 0; i < 8; i++) { v[i] = __expf(v[i] - bm); s += v[i]; }
    #pragma unroll
    for (int o = 16; o; o >>= 1) s += __shfl_xor_sync(~0u, s, o);
    if (lane == 0) sm[warp] = s;
    __syncthreads();
    float tot = 0.f;
    #pragma unroll
    for (int i = 0; i < 8; i++) tot += sm[i];
    const float inv = 1.0f / tot;
    #pragma unroll
    for (int i = 0; i < 8; i++) p[t + 256 * i] = v[i] * inv;
}

// ------------------------------- launch ------------------------------------
static float* sym(const void* s)
{
    void* p = nullptr;
    cudaGetSymbolAddress(&p, s);
    return (float*)p;
}

extern "C" void kernel_launch(void* const* d_in, const int* in_sizes, int n_in,
                              void* d_out, int out_size)
{
    const float* x            = (const float*)d_in[0];
    const float* kv_down_w    = (const float*)d_in[1];
    const float* kv_down_b    = (const float*)d_in[2];
    const float* key_up_w     = (const float*)d_in[3];
    const float* key_up_b     = (const float*)d_in[4];
    const float* value_up_w   = (const float*)d_in[5];
    const float* value_up_b   = (const float*)d_in[6];
    const float* key_rope_w   = (const float*)d_in[7];
    const float* key_rope_b   = (const float*)d_in[8];
    const float* query_down_w = (const float*)d_in[9];
    const float* query_down_b = (const float*)d_in[10];
    const float* query_up_w   = (const float*)d_in[11];
    const float* query_up_b   = (const float*)d_in[12];
    const float* query_rope_w = (const float*)d_in[13];
    const float* query_rope_b = (const float*)d_in[14];
    const float* out_w        = (const float*)d_in[15];
    const float* out_b        = (const float*)d_in[16];
    float* out = (float*)d_out;

    float* kv_c  = sym(g_kv_c);
    float* q_c   = sym(g_q_c);
    float* kcraw = sym(g_kcraw);
    float* qcraw = sym(g_qcraw);
    float* kr    = sym(g_kr);
    float* qr    = sym(g_qr);
    float* Kbuf  = sym(g_K);
    float* Qbuf  = sym(g_Q);
    float* Vbuf  = sym(g_V);
    float* Sbuf  = sym(g_S);
    float* ctx   = sym(g_ctx);

    const float scale = 1.0f / sqrtf((float)DKR);
    auto grid = [](int M, int N, int Z) { return dim3(N / 128, M / 128, Z); };

    // down projections
    tgemm<true><<<grid(SEQ, KVC, 1), 256>>>(SEQ, KVC, HID, 1.f,
        x, HID, 0, kv_down_w, HID, 0, kv_down_b, kv_c, KVC, 0);
    tgemm<true><<<grid(SEQ, QC, 1), 256>>>(SEQ, QC, HID, 1.f,
        x, HID, 0, query_down_w, HID, 0, query_down_b, q_c, QC, 0);

    // up projections
    tgemm<true><<<grid(SEQ, HID, 1), 256>>>(SEQ, HID, KVC, 1.f,
        kv_c, KVC, 0, key_up_w, KVC, 0, key_up_b, kcraw, HID, 0);
    tgemm<true><<<grid(SEQ, HID, 1), 256>>>(SEQ, HID, KVC, 1.f,
        kv_c, KVC, 0, value_up_w, KVC, 0, value_up_b, Vbuf, HID, 0);
    tgemm<true><<<grid(SEQ, NH * RD, 1), 256>>>(SEQ, NH * RD, KVC, 1.f,
        kv_c, KVC, 0, key_rope_w, KVC, 0, key_rope_b, kr, NH * RD, 0);
    tgemm<true><<<grid(SEQ, HID, 1), 256>>>(SEQ, HID, QC, 1.f,
        q_c, QC, 0, query_up_w, QC, 0, query_up_b, qcraw, HID, 0);
    tgemm<true><<<grid(SEQ, NH * RD, 1), 256>>>(SEQ, NH * RD, QC, 1.f,
        q_c, QC, 0, query_rope_w, QC, 0, query_rope_b, qr, NH * RD, 0);

    // pack into [S, H, 192] with RoPE
    pack_c<<<SEQ * HID / 256, 256>>>(kcraw, Kbuf);
    pack_rope<<<SEQ * NH * 32 / 256, 256>>>(kr, Kbuf);
    pack_c<<<SEQ * HID / 256, 256>>>(qcraw, Qbuf);
    pack_rope<<<SEQ * NH * 32 / 256, 256>>>(qr, Qbuf);

    // scores = scale * Q K^T  (batched over heads), K padded: 192 % 16 == 0
    tgemm<true><<<grid(SEQ, SEQ, NH), 256>>>(SEQ, SEQ, DKR, scale,
        Qbuf, HDK, (size_t)DKR, Kbuf, HDK, (size_t)DKR, nullptr,
        Sbuf, SEQ, (size_t)SEQ * SEQ);

    // softmax over last dim
    softmax_rows<<<NH * SEQ, 256>>>(Sbuf);

    // ctx = P @ V  (batched over heads, NN)
    tgemm<false><<<grid(SEQ, HD, NH), 256>>>(SEQ, HD, SEQ, 1.f,
        Sbuf, SEQ, (size_t)SEQ * SEQ, Vbuf, HID, (size_t)HD, nullptr,
        ctx, HID, (size_t)HD);

    // output projection
    tgemm<true><<<grid(SEQ, HID, 1), 256>>>(SEQ, HID, HID, 1.f,
        ctx, HID, 0, out_w, HID, 0, out_b, out, HID, 0);
}